// round 8
// baseline (speedup 1.0000x reference)
#include <cuda_runtime.h>
#include <cstdint>
#include <cstddef>

// RNN_49297634623576: out = fc_w @ tanh(w_ih @ x[:,27,:] + b_ih + b_hh) + fc_b
// hx == 0 => w_hh unused.
//
// R8: 7 rounds pinned at 19-21us / issue ~30% regardless of structure or warp
// count => the shared resource is the smem LDS port (crossbar-effective
// ~1 LDS / 4 cyc at nw>=4; every kernel was ~30% LDS). Fix: remove LDS from
// the loop entirely. Weights (~10KB) are copied into __constant__ via
// cudaMemcpyToSymbolAsync (D2D, graph-capturable, alloc-free) and read with
// LDC/LDCU on the separate constant port. No shared memory, no syncthreads.
// Biases fold free: layer-1 accumulator inits to {b_ih[j], b_hh[j]} (halves
// sum in hsum2); fc_b pre-folded into FC accumulator init.

#define NB   65536
#define NIN  28
#define NHID 64
#define NOUT 10
#define TPB  128   // 1 row/thread -> 512 CTAs, 2048 warps

typedef unsigned long long u64;

__constant__ ulonglong2 c_w[NHID * 7];   // w_ih raw [64][28]: 7x16B per row
__constant__ float      c_bih[NHID];
__constant__ float      c_bhh[NHID];
__constant__ float      c_fcw[NOUT * NHID];  // fc_w raw [10][64]
__constant__ float      c_fcb[NOUT];

__device__ __forceinline__ u64 pk2(float a, float b) {
    u64 r; asm("mov.b64 %0,{%1,%2};" : "=l"(r) : "f"(a), "f"(b)); return r;
}
__device__ __forceinline__ void upk2(u64 v, float& a, float& b) {
    asm("mov.b64 {%0,%1},%2;" : "=f"(a), "=f"(b) : "l"(v));
}
__device__ __forceinline__ u64 ffma2(u64 a, u64 b, u64 c) {
    u64 d; asm("fma.rn.f32x2 %0,%1,%2,%3;" : "=l"(d) : "l"(a), "l"(b), "l"(c)); return d;
}
__device__ __forceinline__ float hsum2(u64 v) {
    float a, b; upk2(v, a, b); return a + b;
}

// tanh(x) = 1 - 2*rcp(exp2(x*2log2e)+1); ~1e-6 accurate.
__device__ __forceinline__ float tanh_fast(float x) {
    const float LOG2E_X2 = 2.8853900817779268f;
    float e, r;
    asm("ex2.approx.ftz.f32 %0, %1;" : "=f"(e) : "f"(x * LOG2E_X2));
    asm("rcp.approx.ftz.f32 %0, %1;" : "=f"(r) : "f"(e + 1.0f));
    return fmaf(-2.0f, r, 1.0f);
}

__global__ void __launch_bounds__(TPB, 6)
rnn_fused_kernel(const float* __restrict__ x, float* __restrict__ out)
{
    const int row = blockIdx.x * TPB + threadIdx.x;   // one batch row per thread

    // Last 28 floats of this row; float offset 756 is 16B aligned.
    u64 in[NIN / 2];
    {
        const float4* p = reinterpret_cast<const float4*>(x + (size_t)row * 784 + 756);
#pragma unroll
        for (int q = 0; q < 7; q++) {
            float4 v = p[q];
            in[2 * q]     = pk2(v.x, v.y);
            in[2 * q + 1] = pk2(v.z, v.w);
        }
    }

    // FC accumulators {out[2q], out[2q+1]}, fc bias pre-folded.
    u64 oa[NOUT / 2];
#pragma unroll
    for (int q = 0; q < NOUT / 2; q++) oa[q] = pk2(c_fcb[2 * q], c_fcb[2 * q + 1]);

#pragma unroll 4
    for (int j = 0; j < NHID; j++) {
        // Layer 1: accumulator starts as {b_ih[j], b_hh[j]} — halves sum in hsum2.
        u64 a = pk2(c_bih[j], c_bhh[j]);
#pragma unroll
        for (int q = 0; q < 7; q++) {
            ulonglong2 w = c_w[j * 7 + q];        // LDC.128 / LDCU — const port
            a = ffma2(w.x, in[2 * q], a);
            a = ffma2(w.y, in[2 * q + 1], a);
        }
        float h = tanh_fast(hsum2(a));
        u64 hp = pk2(h, h);
#pragma unroll
        for (int q = 0; q < NOUT / 2; q++) {
            u64 fw = pk2(c_fcw[(2 * q) * NHID + j], c_fcw[(2 * q + 1) * NHID + j]);
            oa[q] = ffma2(fw, hp, oa[q]);
        }
    }

    // Store 10 floats = 5x STG.64 (40B row stride -> 8B aligned).
    float2* o2 = reinterpret_cast<float2*>(out + (size_t)row * NOUT);
#pragma unroll
    for (int q = 0; q < NOUT / 2; q++) {
        float a, b;
        upk2(oa[q], a, b);
        o2[q] = make_float2(a, b);
    }
}

extern "C" void kernel_launch(void* const* d_in, const int* in_sizes, int n_in,
                              void* d_out, int out_size)
{
    (void)in_sizes; (void)n_in; (void)out_size;
    const float* x = (const float*)d_in[0];
    // d_in[2] = w_hh : unused (hx == 0)

    // Stage weights into constant memory. Async D2D memcpys on the same
    // stream as the kernel -> graph-capturable memcpy nodes, ordered before
    // the kernel launch. No allocation, runs identically on every replay.
    cudaMemcpyToSymbolAsync(c_w,    d_in[1], NHID * NIN * sizeof(float), 0,
                            cudaMemcpyDeviceToDevice, 0);
    cudaMemcpyToSymbolAsync(c_bih,  d_in[3], NHID * sizeof(float), 0,
                            cudaMemcpyDeviceToDevice, 0);
    cudaMemcpyToSymbolAsync(c_bhh,  d_in[4], NHID * sizeof(float), 0,
                            cudaMemcpyDeviceToDevice, 0);
    cudaMemcpyToSymbolAsync(c_fcw,  d_in[5], NOUT * NHID * sizeof(float), 0,
                            cudaMemcpyDeviceToDevice, 0);
    cudaMemcpyToSymbolAsync(c_fcb,  d_in[6], NOUT * sizeof(float), 0,
                            cudaMemcpyDeviceToDevice, 0);

    float* out = (float*)d_out;
    const int blocks = NB / TPB;   // 512, exact
    rnn_fused_kernel<<<blocks, TPB>>>(x, out);
}

// round 9
// speedup vs baseline: 1.7467x; 1.7467x over previous
#include <cuda_runtime.h>
#include <cstdint>
#include <cstddef>

// RNN_49297634623576: out = fc_w @ tanh(w_ih @ x[:,27,:] + b_ih + b_hh) + fc_b
// hx == 0 => w_hh unused.
//
// R9 model (fits all 8 rounds): binder is the L1TEX wavefront FIFO (~1 wf/cyc
// /SM; LDS.128=2 wf even broadcast). R5: 18.5k wf/SM == L1 50.7% exactly;
// bursty 40-wf iterations inflate effective LDS latency to ~100-150cyc ->
// issue pinned ~30% independent of warp count. Total wf = warps x reread
// bytes/8 ~ 1/R^2.
// Fix: R=4 rows/thread (amortize every weight read 4x) AND hidden-split s=2
// across warps (keep 1024 warps): 4.6k wf/SM (4x lower), 4 independent
// chains in every section. CTA=2 warps/128 rows, 512 CTAs.

#define NB   65536
#define NIN  28
#define NHID 64
#define NOUT 10
#define TPB  64    // 2 warps; 128 rows/CTA -> 512 CTAs

typedef unsigned long long u64;

__device__ __forceinline__ u64 pk2(float a, float b) {
    u64 r; asm("mov.b64 %0,{%1,%2};" : "=l"(r) : "f"(a), "f"(b)); return r;
}
__device__ __forceinline__ void upk2(u64 v, float& a, float& b) {
    asm("mov.b64 {%0,%1},%2;" : "=f"(a), "=f"(b) : "l"(v));
}
__device__ __forceinline__ u64 ffma2(u64 a, u64 b, u64 c) {
    u64 d; asm("fma.rn.f32x2 %0,%1,%2,%3;" : "=l"(d) : "l"(a), "l"(b), "l"(c)); return d;
}
__device__ __forceinline__ u64 fadd2(u64 a, u64 b) {
    u64 d; asm("add.rn.f32x2 %0,%1,%2;" : "=l"(d) : "l"(a), "l"(b)); return d;
}
__device__ __forceinline__ float hsum2(u64 v) {
    float a, b; upk2(v, a, b); return a + b;
}

// tanh(x) = 1 - 2*rcp(exp2(x*2log2e)+1); ~1e-6 accurate.
__device__ __forceinline__ float tanh_fast(float x) {
    const float LOG2E_X2 = 2.8853900817779268f;
    float e, r;
    asm("ex2.approx.ftz.f32 %0, %1;" : "=f"(e) : "f"(x * LOG2E_X2));
    asm("rcp.approx.ftz.f32 %0, %1;" : "=f"(r) : "f"(e + 1.0f));
    return fmaf(-2.0f, r, 1.0f);
}

__global__ void __launch_bounds__(TPB, 4)
rnn_fused_kernel(const float* __restrict__ x,
                 const float* __restrict__ w_ih,
                 const float* __restrict__ b_ih,
                 const float* __restrict__ b_hh,
                 const float* __restrict__ fc_w,
                 const float* __restrict__ fc_b,
                 float* __restrict__ out)
{
    // Row j (128B): [0..13]={w[j][2p],w[j][2p+1]}, [14]={bias_j,0}, [15]=0.
    __shared__ u64 s_w[NHID][16];
    // Row j: [q<5]={fc_w[2q][j], fc_w[2q+1][j]}, [5]=0.
    __shared__ u64 s_fck[NHID][6];
    __shared__ u64 s_fcb[NOUT / 2];
    // FC partials: [warp][component][row_local]; 8B lane stride -> conflict-free.
    __shared__ u64 s_part[2][NOUT / 2][128];

    const int tid  = threadIdx.x;
    const int wid  = tid >> 5;
    const int lane = tid & 31;

    for (int i = tid; i < NHID * (NIN / 2); i += TPB) {
        int j = i / (NIN / 2), p = i % (NIN / 2);
        s_w[j][p] = pk2(w_ih[j * NIN + 2 * p], w_ih[j * NIN + 2 * p + 1]);
    }
    for (int i = tid; i < NHID; i += TPB) {
        s_w[i][14] = pk2(b_ih[i] + b_hh[i], 0.0f);
        s_w[i][15] = 0ull;
    }
    for (int i = tid; i < NHID * (NOUT / 2); i += TPB) {
        int j = i / (NOUT / 2), q = i % (NOUT / 2);
        s_fck[j][q] = pk2(fc_w[(2 * q) * NHID + j], fc_w[(2 * q + 1) * NHID + j]);
    }
    for (int i = tid; i < NHID; i += TPB) s_fck[i][5] = 0ull;
    if (tid < NOUT / 2) s_fcb[tid] = pk2(fc_b[2 * tid], fc_b[2 * tid + 1]);
    __syncthreads();

    const int rbase = blockIdx.x << 7;      // 128 rows per CTA
    const int jbase = wid << 5;             // warp owns 32 hidden units

    // Inputs: 4 rows per thread, row_local = i*32 + lane.
    u64 in[4][NIN / 2];
#pragma unroll
    for (int i = 0; i < 4; i++) {
        const int r = rbase + (i << 5) + lane;
        const float4* p = reinterpret_cast<const float4*>(x + (size_t)r * 784 + 756);
#pragma unroll
        for (int q = 0; q < 7; q++) {
            float4 v = p[q];
            in[i][2 * q]     = pk2(v.x, v.y);
            in[i][2 * q + 1] = pk2(v.z, v.w);
        }
    }

    // FC partial accumulators {out[2q], out[2q+1]} per row (bias added in reduce).
    u64 oa[4][NOUT / 2];
#pragma unroll
    for (int i = 0; i < 4; i++)
#pragma unroll
        for (int q = 0; q < NOUT / 2; q++) oa[i][q] = 0ull;

#pragma unroll 2
    for (int jj = 0; jj < 32; jj++) {
        const int j = jbase + jj;
        // Weight row: 8 broadcast LDS.128 (16 wavefronts), batched.
        const ulonglong2* wr = reinterpret_cast<const ulonglong2*>(&s_w[j][0]);
        ulonglong2 W[8];
#pragma unroll
        for (int q = 0; q < 8; q++) W[q] = wr[q];

        // Layer 1: 4 independent FFMA2 chains (one per row), bias pre-seeded.
        u64 a0 = W[7].x, a1 = W[7].x, a2 = W[7].x, a3 = W[7].x;
#pragma unroll
        for (int p = 0; p < 7; p++) {
            a0 = ffma2(W[p].x, in[0][2 * p], a0);
            a1 = ffma2(W[p].x, in[1][2 * p], a1);
            a2 = ffma2(W[p].x, in[2][2 * p], a2);
            a3 = ffma2(W[p].x, in[3][2 * p], a3);
            a0 = ffma2(W[p].y, in[0][2 * p + 1], a0);
            a1 = ffma2(W[p].y, in[1][2 * p + 1], a1);
            a2 = ffma2(W[p].y, in[2][2 * p + 1], a2);
            a3 = ffma2(W[p].y, in[3][2 * p + 1], a3);
        }

        // 4 parallel tanh chains.
        float h0 = tanh_fast(hsum2(a0));
        float h1 = tanh_fast(hsum2(a1));
        float h2 = tanh_fast(hsum2(a2));
        float h3 = tanh_fast(hsum2(a3));
        u64 hp0 = pk2(h0, h0), hp1 = pk2(h1, h1);
        u64 hp2 = pk2(h2, h2), hp3 = pk2(h3, h3);

        // FC: 5 k-pair weights (2x LDS.128 + 1x LDS.64 = 5 wf), 20 FFMA2, 20 chains.
        const ulonglong2* fr = reinterpret_cast<const ulonglong2*>(&s_fck[j][0]);
        ulonglong2 fA = fr[0], fB = fr[1];
        u64 fE = s_fck[j][4];
        oa[0][0] = ffma2(fA.x, hp0, oa[0][0]);
        oa[1][0] = ffma2(fA.x, hp1, oa[1][0]);
        oa[2][0] = ffma2(fA.x, hp2, oa[2][0]);
        oa[3][0] = ffma2(fA.x, hp3, oa[3][0]);
        oa[0][1] = ffma2(fA.y, hp0, oa[0][1]);
        oa[1][1] = ffma2(fA.y, hp1, oa[1][1]);
        oa[2][1] = ffma2(fA.y, hp2, oa[2][1]);
        oa[3][1] = ffma2(fA.y, hp3, oa[3][1]);
        oa[0][2] = ffma2(fB.x, hp0, oa[0][2]);
        oa[1][2] = ffma2(fB.x, hp1, oa[1][2]);
        oa[2][2] = ffma2(fB.x, hp2, oa[2][2]);
        oa[3][2] = ffma2(fB.x, hp3, oa[3][2]);
        oa[0][3] = ffma2(fB.y, hp0, oa[0][3]);
        oa[1][3] = ffma2(fB.y, hp1, oa[1][3]);
        oa[2][3] = ffma2(fB.y, hp2, oa[2][3]);
        oa[3][3] = ffma2(fB.y, hp3, oa[3][3]);
        oa[0][4] = ffma2(fE, hp0, oa[0][4]);
        oa[1][4] = ffma2(fE, hp1, oa[1][4]);
        oa[2][4] = ffma2(fE, hp2, oa[2][4]);
        oa[3][4] = ffma2(fE, hp3, oa[3][4]);
    }

    // Publish this warp's partials (conflict-free STS.64: 8B lane stride).
#pragma unroll
    for (int i = 0; i < 4; i++) {
        const int rl = (i << 5) + lane;
#pragma unroll
        for (int q = 0; q < NOUT / 2; q++) s_part[wid][q][rl] = oa[i][q];
    }
    __syncthreads();

    // Combine warp halves + fc bias, store. 64 threads x 2 rows each.
#pragma unroll
    for (int rr = tid; rr < 128; rr += TPB) {
        float2* o2 = reinterpret_cast<float2*>(out + (size_t)(rbase + rr) * NOUT);
#pragma unroll
        for (int q = 0; q < NOUT / 2; q++) {
            u64 v = fadd2(fadd2(s_part[0][q][rr], s_part[1][q][rr]), s_fcb[q]);
            float a, b;
            upk2(v, a, b);
            o2[q] = make_float2(a, b);
        }
    }
}

extern "C" void kernel_launch(void* const* d_in, const int* in_sizes, int n_in,
                              void* d_out, int out_size)
{
    (void)in_sizes; (void)n_in; (void)out_size;
    const float* x    = (const float*)d_in[0];
    const float* w_ih = (const float*)d_in[1];
    // d_in[2] = w_hh : unused (hx == 0)
    const float* b_ih = (const float*)d_in[3];
    const float* b_hh = (const float*)d_in[4];
    const float* fc_w = (const float*)d_in[5];
    const float* fc_b = (const float*)d_in[6];
    float* out = (float*)d_out;

    const int blocks = NB / 128;   // 512, exact

    rnn_fused_kernel<<<blocks, TPB>>>(x, w_ih, b_ih, b_hh, fc_w, fc_b, out);
}

// round 10
// speedup vs baseline: 1.7733x; 1.0152x over previous
#include <cuda_runtime.h>
#include <cstdint>
#include <cstddef>

// RNN_49297634623576: out = fc_w @ tanh(w_ih @ x[:,27,:] + b_ih + b_hh) + fc_b
// hx == 0 => w_hh unused.
//
// R10: R8's failure was GPR-dest LDC (floor 8/SMSP) from runtime const
// addresses under `unroll 4` (33k cyc == measured). Fix: FULL unroll -> every
// const address is an immediate -> uniform-port LDCU (floor 1/SMSP, off the
// LSU). Layer-1 weight pairs are adjacent in raw w_ih => direct 64-bit const
// reads, no packing. FC weights stay on the (now idle) smem port: the two
// load streams ride different HW ports. Shape: 1 row/thread, TPB=128,
// 512 CTAs (~2048 warps).

#define NB   65536
#define NIN  28
#define NHID 64
#define NOUT 10
#define TPB  128   // 1 row/thread -> 512 CTAs

typedef unsigned long long u64;

__constant__ u64   c_w64[NHID * NIN / 2];  // raw w_ih bytes: [j][p] = {w[j][2p], w[j][2p+1]}
__constant__ float c_bih[NHID];
__constant__ float c_bhh[NHID];

__device__ __forceinline__ u64 pk2(float a, float b) {
    u64 r; asm("mov.b64 %0,{%1,%2};" : "=l"(r) : "f"(a), "f"(b)); return r;
}
__device__ __forceinline__ void upk2(u64 v, float& a, float& b) {
    asm("mov.b64 {%0,%1},%2;" : "=f"(a), "=f"(b) : "l"(v));
}
__device__ __forceinline__ u64 ffma2(u64 a, u64 b, u64 c) {
    u64 d; asm("fma.rn.f32x2 %0,%1,%2,%3;" : "=l"(d) : "l"(a), "l"(b), "l"(c)); return d;
}
__device__ __forceinline__ float hsum2(u64 v) {
    float a, b; upk2(v, a, b); return a + b;
}

// tanh(x) = 1 - 2*rcp(exp2(x*2log2e)+1); ~1e-6 accurate.
__device__ __forceinline__ float tanh_fast(float x) {
    const float LOG2E_X2 = 2.8853900817779268f;
    float e, r;
    asm("ex2.approx.ftz.f32 %0, %1;" : "=f"(e) : "f"(x * LOG2E_X2));
    asm("rcp.approx.ftz.f32 %0, %1;" : "=f"(r) : "f"(e + 1.0f));
    return fmaf(-2.0f, r, 1.0f);
}

__global__ void __launch_bounds__(TPB, 6)
rnn_fused_kernel(const float* __restrict__ x,
                 const float* __restrict__ fc_w,
                 const float* __restrict__ fc_b,
                 float* __restrict__ out)
{
    // FC weights on the smem port: [j][q<5] = {fc_w[2q][j], fc_w[2q+1][j]}.
    __shared__ u64 s_fck[NHID][6];
    __shared__ u64 s_fcb[NOUT / 2];

    const int tid = threadIdx.x;

    for (int i = tid; i < NHID * (NOUT / 2); i += TPB) {
        int j = i / (NOUT / 2), q = i % (NOUT / 2);
        s_fck[j][q] = pk2(fc_w[(2 * q) * NHID + j], fc_w[(2 * q + 1) * NHID + j]);
    }
    for (int i = tid; i < NHID; i += TPB) s_fck[i][5] = 0ull;
    if (tid < NOUT / 2) s_fcb[tid] = pk2(fc_b[2 * tid], fc_b[2 * tid + 1]);
    __syncthreads();

    const int row = blockIdx.x * TPB + tid;   // one batch row per thread

    // Last 28 floats of this row; float offset 756 is 16B aligned.
    u64 in[NIN / 2];
    {
        const float4* p = reinterpret_cast<const float4*>(x + (size_t)row * 784 + 756);
#pragma unroll
        for (int q = 0; q < 7; q++) {
            float4 v = p[q];
            in[2 * q]     = pk2(v.x, v.y);
            in[2 * q + 1] = pk2(v.z, v.w);
        }
    }

    // FC accumulators {out[2q], out[2q+1]}, fc bias pre-folded.
    u64 oa[NOUT / 2];
#pragma unroll
    for (int q = 0; q < NOUT / 2; q++) oa[q] = s_fcb[q];

    // FULL unroll: every c_* access below has a compile-time immediate
    // address -> uniform-port LDCU (floor 1/SMSP), zero LSU involvement.
#pragma unroll
    for (int j = 0; j < NHID; j++) {
        // Accumulator seeded {b_ih[j], b_hh[j]}: both biases sum in hsum2.
        u64 a = pk2(c_bih[j], c_bhh[j]);
#pragma unroll
        for (int p = 0; p < NIN / 2; p++) {
            a = ffma2(c_w64[j * (NIN / 2) + p], in[p], a);
        }
        float h = tanh_fast(hsum2(a));
        u64 hp = pk2(h, h);

        // FC on the smem port: 2x LDS.128 + 1x LDS.64 (broadcast).
        const ulonglong2* fr = reinterpret_cast<const ulonglong2*>(&s_fck[j][0]);
        ulonglong2 fA = fr[0], fB = fr[1];
        u64 fE = s_fck[j][4];
        oa[0] = ffma2(fA.x, hp, oa[0]);
        oa[1] = ffma2(fA.y, hp, oa[1]);
        oa[2] = ffma2(fB.x, hp, oa[2]);
        oa[3] = ffma2(fB.y, hp, oa[3]);
        oa[4] = ffma2(fE,   hp, oa[4]);
    }

    // Store 10 floats = 5x STG.64 (40B row stride -> 8B aligned).
    float2* o2 = reinterpret_cast<float2*>(out + (size_t)row * NOUT);
#pragma unroll
    for (int q = 0; q < NOUT / 2; q++) {
        float a, b;
        upk2(oa[q], a, b);
        o2[q] = make_float2(a, b);
    }
}

extern "C" void kernel_launch(void* const* d_in, const int* in_sizes, int n_in,
                              void* d_out, int out_size)
{
    (void)in_sizes; (void)n_in; (void)out_size;
    const float* x    = (const float*)d_in[0];
    // d_in[2] = w_hh : unused (hx == 0)
    const float* fc_w = (const float*)d_in[5];
    const float* fc_b = (const float*)d_in[6];
    float* out = (float*)d_out;

    // Stage layer-1 weights/biases into constant memory (async D2D memcpys:
    // graph-capturable nodes, alloc-free, ordered before the kernel).
    cudaMemcpyToSymbolAsync(c_w64, d_in[1], NHID * NIN * sizeof(float), 0,
                            cudaMemcpyDeviceToDevice, 0);
    cudaMemcpyToSymbolAsync(c_bih, d_in[3], NHID * sizeof(float), 0,
                            cudaMemcpyDeviceToDevice, 0);
    cudaMemcpyToSymbolAsync(c_bhh, d_in[4], NHID * sizeof(float), 0,
                            cudaMemcpyDeviceToDevice, 0);

    const int blocks = NB / TPB;   // 512, exact
    rnn_fused_kernel<<<blocks, TPB>>>(x, fc_w, fc_b, out);
}

// round 11
// speedup vs baseline: 1.7763x; 1.0017x over previous
#include <cuda_runtime.h>
#include <cstdint>
#include <cstddef>

// RNN_49297634623576: out = fc_w @ tanh(w_ih @ x[:,27,:] + b_ih + b_hh) + fc_b
// hx == 0 => w_hh unused.
//
// R11 model (fits R1-R10): issue = warps_per_SMSP / g (g = per-warp stall gap,
// ~11 cyc, irreducible here). R10: 3.46/11 = 0.31 == measured. Levers: raise
// nw WITHOUT re-inflating g (R6: LDS-queue, R4: conflicts, R8: LDC floor).
// R10's LDCU layer-1 has ~zero LDS wavefronts -> safe to double warps:
// split hidden dim across WARPS (warp owns 32 j), 4096 warps, 1024 CTAs,
// 7 CTAs/SM -> 6.9 warps/SMSP. Half-selection via warp-uniform branch into
// two fully-unrolled template bodies so every LDCU address stays an
// immediate (R8 lesson: runtime base -> GPR LDC at floor 8).

#define NB   65536
#define NIN  28
#define NHID 64
#define NOUT 10
#define TPB  128   // 4 warps: (half, rowgroup); 64 rows/CTA -> 1024 CTAs

typedef unsigned long long u64;

__constant__ u64   c_w64[NHID * NIN / 2];  // raw w_ih: [j][p] = {w[j][2p], w[j][2p+1]}
__constant__ float c_bih[NHID];
__constant__ float c_bhh[NHID];

__device__ __forceinline__ u64 pk2(float a, float b) {
    u64 r; asm("mov.b64 %0,{%1,%2};" : "=l"(r) : "f"(a), "f"(b)); return r;
}
__device__ __forceinline__ void upk2(u64 v, float& a, float& b) {
    asm("mov.b64 {%0,%1},%2;" : "=f"(a), "=f"(b) : "l"(v));
}
__device__ __forceinline__ u64 ffma2(u64 a, u64 b, u64 c) {
    u64 d; asm("fma.rn.f32x2 %0,%1,%2,%3;" : "=l"(d) : "l"(a), "l"(b), "l"(c)); return d;
}
__device__ __forceinline__ u64 fadd2(u64 a, u64 b) {
    u64 d; asm("add.rn.f32x2 %0,%1,%2;" : "=l"(d) : "l"(a), "l"(b)); return d;
}
__device__ __forceinline__ float hsum2(u64 v) {
    float a, b; upk2(v, a, b); return a + b;
}

// tanh(x) = 1 - 2*rcp(exp2(x*2log2e)+1); ~1e-6 accurate.
__device__ __forceinline__ float tanh_fast(float x) {
    const float LOG2E_X2 = 2.8853900817779268f;
    float e, r;
    asm("ex2.approx.ftz.f32 %0, %1;" : "=f"(e) : "f"(x * LOG2E_X2));
    asm("rcp.approx.ftz.f32 %0, %1;" : "=f"(r) : "f"(e + 1.0f));
    return fmaf(-2.0f, r, 1.0f);
}

// One half's work: 32 hidden units [JBASE, JBASE+32). Fully unrolled so every
// constant access is a compile-time immediate -> uniform-port LDCU.
template <int JBASE>
__device__ __forceinline__ void half_work(const u64 (&in)[NIN / 2],
                                          const u64 (*s_fck)[6],
                                          u64 (&oa)[NOUT / 2])
{
#pragma unroll
    for (int jj = 0; jj < 32; jj++) {
        const int j = JBASE + jj;
        u64 a = pk2(c_bih[j], c_bhh[j]);   // both biases sum in hsum2
#pragma unroll
        for (int p = 0; p < NIN / 2; p++) {
            a = ffma2(c_w64[j * (NIN / 2) + p], in[p], a);
        }
        float h = tanh_fast(hsum2(a));
        u64 hp = pk2(h, h);

        const ulonglong2* fr = reinterpret_cast<const ulonglong2*>(&s_fck[j][0]);
        ulonglong2 fA = fr[0], fB = fr[1];
        u64 fE = s_fck[j][4];
        oa[0] = ffma2(fA.x, hp, oa[0]);
        oa[1] = ffma2(fA.y, hp, oa[1]);
        oa[2] = ffma2(fB.x, hp, oa[2]);
        oa[3] = ffma2(fB.y, hp, oa[3]);
        oa[4] = ffma2(fE,   hp, oa[4]);
    }
}

__global__ void __launch_bounds__(TPB, 7)
rnn_fused_kernel(const float* __restrict__ x,
                 const float* __restrict__ fc_w,
                 const float* __restrict__ fc_b,
                 float* __restrict__ out)
{
    // FC weights on smem port: [j][q<5] = {fc_w[2q][j], fc_w[2q+1][j]}.
    __shared__ u64 s_fck[NHID][6];
    __shared__ u64 s_fcb[NOUT / 2];
    // Half-0 partials: [component][row_local]; 8B lane stride -> conflict-free.
    __shared__ u64 s_part[NOUT / 2][64];

    const int tid = threadIdx.x;

    for (int i = tid; i < NHID * (NOUT / 2); i += TPB) {
        int j = i / (NOUT / 2), q = i % (NOUT / 2);
        s_fck[j][q] = pk2(fc_w[(2 * q) * NHID + j], fc_w[(2 * q + 1) * NHID + j]);
    }
    for (int i = tid; i < NHID; i += TPB) s_fck[i][5] = 0ull;
    if (tid < NOUT / 2) s_fcb[tid] = pk2(fc_b[2 * tid], fc_b[2 * tid + 1]);
    __syncthreads();

    const int wid  = tid >> 5;
    const int lane = tid & 31;
    const int half = wid & 1;              // which 32 hidden units
    const int rloc = ((wid >> 1) << 5) + lane;   // row within CTA (0..63)
    const int row  = (blockIdx.x << 6) + rloc;

    // Last 28 floats of this row; float offset 756 is 16B aligned.
    u64 in[NIN / 2];
    {
        const float4* p = reinterpret_cast<const float4*>(x + (size_t)row * 784 + 756);
#pragma unroll
        for (int q = 0; q < 7; q++) {
            float4 v = p[q];
            in[2 * q]     = pk2(v.x, v.y);
            in[2 * q + 1] = pk2(v.z, v.w);
        }
    }

    u64 oa[NOUT / 2];
#pragma unroll
    for (int q = 0; q < NOUT / 2; q++) oa[q] = 0ull;

    // Warp-uniform branch: each instantiation has immediate const addresses.
    if (half == 0) half_work<0>(in, s_fck, oa);
    else           half_work<32>(in, s_fck, oa);

    // Half 0 publishes partials; half 1 combines (+ fc bias) and stores.
    if (half == 0) {
#pragma unroll
        for (int q = 0; q < NOUT / 2; q++) s_part[q][rloc] = oa[q];
    }
    __syncthreads();
    if (half == 1) {
        float2* o2 = reinterpret_cast<float2*>(out + (size_t)row * NOUT);
#pragma unroll
        for (int q = 0; q < NOUT / 2; q++) {
            u64 v = fadd2(fadd2(oa[q], s_part[q][rloc]), s_fcb[q]);
            float a, b;
            upk2(v, a, b);
            o2[q] = make_float2(a, b);
        }
    }
}

extern "C" void kernel_launch(void* const* d_in, const int* in_sizes, int n_in,
                              void* d_out, int out_size)
{
    (void)in_sizes; (void)n_in; (void)out_size;
    const float* x    = (const float*)d_in[0];
    // d_in[2] = w_hh : unused (hx == 0)
    const float* fc_w = (const float*)d_in[5];
    const float* fc_b = (const float*)d_in[6];
    float* out = (float*)d_out;

    // Stage layer-1 weights/biases into constant memory (async D2D memcpys:
    // graph-capturable nodes, alloc-free, ordered before the kernel).
    cudaMemcpyToSymbolAsync(c_w64, d_in[1], NHID * NIN * sizeof(float), 0,
                            cudaMemcpyDeviceToDevice, 0);
    cudaMemcpyToSymbolAsync(c_bih, d_in[3], NHID * sizeof(float), 0,
                            cudaMemcpyDeviceToDevice, 0);
    cudaMemcpyToSymbolAsync(c_bhh, d_in[4], NHID * sizeof(float), 0,
                            cudaMemcpyDeviceToDevice, 0);

    const int blocks = NB / 64;   // 1024, exact
    rnn_fused_kernel<<<blocks, TPB>>>(x, fc_w, fc_b, out);
}

// round 12
// speedup vs baseline: 1.9589x; 1.1028x over previous
#include <cuda_runtime.h>
#include <cstdint>
#include <cstddef>

// RNN_49297634623576: out = fc_w @ tanh(w_ih @ x[:,27,:] + b_ih + b_hh) + fc_b
// hx == 0 => w_hh unused.
//
// R12: R11's kernel hit 15.1us (issue 41%) but bench stayed 18.9 — the gap
// is 3 memcpy nodes in the captured graph (~1.2us each serialized replay).
// Fix: ONE memcpy (w_ih only; LDCU path preserved). Biases move to the idle
// smem port: s_bp[j] = {b_ih[j]+b_hh[j], 0}, one broadcast LDS.64 seed per j.
// Kernel structure unchanged from R11 (warp-split halves, full unroll,
// 1024 CTAs, 7 CTAs/SM).

#define NB   65536
#define NIN  28
#define NHID 64
#define NOUT 10
#define TPB  128   // 4 warps: (half, rowgroup); 64 rows/CTA -> 1024 CTAs

typedef unsigned long long u64;

__constant__ u64 c_w64[NHID * NIN / 2];  // raw w_ih: [j][p] = {w[j][2p], w[j][2p+1]}

__device__ __forceinline__ u64 pk2(float a, float b) {
    u64 r; asm("mov.b64 %0,{%1,%2};" : "=l"(r) : "f"(a), "f"(b)); return r;
}
__device__ __forceinline__ void upk2(u64 v, float& a, float& b) {
    asm("mov.b64 {%0,%1},%2;" : "=f"(a), "=f"(b) : "l"(v));
}
__device__ __forceinline__ u64 ffma2(u64 a, u64 b, u64 c) {
    u64 d; asm("fma.rn.f32x2 %0,%1,%2,%3;" : "=l"(d) : "l"(a), "l"(b), "l"(c)); return d;
}
__device__ __forceinline__ u64 fadd2(u64 a, u64 b) {
    u64 d; asm("add.rn.f32x2 %0,%1,%2;" : "=l"(d) : "l"(a), "l"(b)); return d;
}
__device__ __forceinline__ float hsum2(u64 v) {
    float a, b; upk2(v, a, b); return a + b;
}

// tanh(x) = 1 - 2*rcp(exp2(x*2log2e)+1); ~1e-6 accurate.
__device__ __forceinline__ float tanh_fast(float x) {
    const float LOG2E_X2 = 2.8853900817779268f;
    float e, r;
    asm("ex2.approx.ftz.f32 %0, %1;" : "=f"(e) : "f"(x * LOG2E_X2));
    asm("rcp.approx.ftz.f32 %0, %1;" : "=f"(r) : "f"(e + 1.0f));
    return fmaf(-2.0f, r, 1.0f);
}

// One half's work: 32 hidden units [JBASE, JBASE+32). Fully unrolled so every
// c_w64 access is a compile-time immediate -> uniform-port LDCU.
template <int JBASE>
__device__ __forceinline__ void half_work(const u64 (&in)[NIN / 2],
                                          const u64* s_bp,
                                          const u64 (*s_fck)[6],
                                          u64 (&oa)[NOUT / 2])
{
#pragma unroll
    for (int jj = 0; jj < 32; jj++) {
        const int j = JBASE + jj;
        u64 a = s_bp[j];                    // {b_ih[j]+b_hh[j], 0} broadcast LDS
#pragma unroll
        for (int p = 0; p < NIN / 2; p++) {
            a = ffma2(c_w64[j * (NIN / 2) + p], in[p], a);
        }
        float h = tanh_fast(hsum2(a));
        u64 hp = pk2(h, h);

        const ulonglong2* fr = reinterpret_cast<const ulonglong2*>(&s_fck[j][0]);
        ulonglong2 fA = fr[0], fB = fr[1];
        u64 fE = s_fck[j][4];
        oa[0] = ffma2(fA.x, hp, oa[0]);
        oa[1] = ffma2(fA.y, hp, oa[1]);
        oa[2] = ffma2(fB.x, hp, oa[2]);
        oa[3] = ffma2(fB.y, hp, oa[3]);
        oa[4] = ffma2(fE,   hp, oa[4]);
    }
}

__global__ void __launch_bounds__(TPB, 7)
rnn_fused_kernel(const float* __restrict__ x,
                 const float* __restrict__ b_ih,
                 const float* __restrict__ b_hh,
                 const float* __restrict__ fc_w,
                 const float* __restrict__ fc_b,
                 float* __restrict__ out)
{
    // FC weights on smem port: [j][q<5] = {fc_w[2q][j], fc_w[2q+1][j]}.
    __shared__ u64 s_fck[NHID][6];
    __shared__ u64 s_bp[NHID];          // {b_ih[j]+b_hh[j], 0}
    __shared__ u64 s_fcb[NOUT / 2];
    // Half-0 partials: [component][row_local]; 8B lane stride -> conflict-free.
    __shared__ u64 s_part[NOUT / 2][64];

    const int tid = threadIdx.x;

    for (int i = tid; i < NHID * (NOUT / 2); i += TPB) {
        int j = i / (NOUT / 2), q = i % (NOUT / 2);
        s_fck[j][q] = pk2(fc_w[(2 * q) * NHID + j], fc_w[(2 * q + 1) * NHID + j]);
    }
    for (int i = tid; i < NHID; i += TPB) {
        s_fck[i][5] = 0ull;
        s_bp[i] = pk2(b_ih[i] + b_hh[i], 0.0f);
    }
    if (tid < NOUT / 2) s_fcb[tid] = pk2(fc_b[2 * tid], fc_b[2 * tid + 1]);
    __syncthreads();

    const int wid  = tid >> 5;
    const int lane = tid & 31;
    const int half = wid & 1;                    // which 32 hidden units
    const int rloc = ((wid >> 1) << 5) + lane;   // row within CTA (0..63)
    const int row  = (blockIdx.x << 6) + rloc;

    // Last 28 floats of this row; float offset 756 is 16B aligned.
    u64 in[NIN / 2];
    {
        const float4* p = reinterpret_cast<const float4*>(x + (size_t)row * 784 + 756);
#pragma unroll
        for (int q = 0; q < 7; q++) {
            float4 v = p[q];
            in[2 * q]     = pk2(v.x, v.y);
            in[2 * q + 1] = pk2(v.z, v.w);
        }
    }

    u64 oa[NOUT / 2];
#pragma unroll
    for (int q = 0; q < NOUT / 2; q++) oa[q] = 0ull;

    // Warp-uniform branch: each instantiation has immediate const addresses.
    if (half == 0) half_work<0>(in, s_bp, s_fck, oa);
    else           half_work<32>(in, s_bp, s_fck, oa);

    // Half 0 publishes partials; half 1 combines (+ fc bias) and stores.
    if (half == 0) {
#pragma unroll
        for (int q = 0; q < NOUT / 2; q++) s_part[q][rloc] = oa[q];
    }
    __syncthreads();
    if (half == 1) {
        float2* o2 = reinterpret_cast<float2*>(out + (size_t)row * NOUT);
#pragma unroll
        for (int q = 0; q < NOUT / 2; q++) {
            u64 v = fadd2(fadd2(oa[q], s_part[q][rloc]), s_fcb[q]);
            float a, b;
            upk2(v, a, b);
            o2[q] = make_float2(a, b);
        }
    }
}

extern "C" void kernel_launch(void* const* d_in, const int* in_sizes, int n_in,
                              void* d_out, int out_size)
{
    (void)in_sizes; (void)n_in; (void)out_size;
    const float* x    = (const float*)d_in[0];
    // d_in[2] = w_hh : unused (hx == 0)
    const float* b_ih = (const float*)d_in[3];
    const float* b_hh = (const float*)d_in[4];
    const float* fc_w = (const float*)d_in[5];
    const float* fc_b = (const float*)d_in[6];
    float* out = (float*)d_out;

    // Single staging memcpy: w_ih -> constant (LDCU path). Async D2D,
    // graph-capturable, alloc-free, ordered before the kernel.
    cudaMemcpyToSymbolAsync(c_w64, d_in[1], NHID * NIN * sizeof(float), 0,
                            cudaMemcpyDeviceToDevice, 0);

    const int blocks = NB / 64;   // 1024, exact
    rnn_fused_kernel<<<blocks, TPB>>>(x, b_ih, b_hh, fc_w, fc_b, out);
}